// round 10
// baseline (speedup 1.0000x reference)
#include <cuda_runtime.h>
#include <math.h>

// Shape fixed by reference: B=2, L=2048, H=16, E=64
#define B_  2
#define L_  2048
#define H_  16
#define E_  64
#define BH_ 32            // B*H chains
#define CH_ 64            // chunk length along s
#define NC_ 32            // chunks per chain
#define HE_ 1024          // H*E row stride in floats
#define NBLK (BH_ * NC_)  // 1024 K1 blocks
#define NSUB 4            // sub-groups (16 rows each)
#define RPS  16           // rows per sub

// Scratch (__device__ globals; no allocations allowed)
__device__ float  g_E   [BH_ * L_];          // e-scores
__device__ float4 g_agg [NBLK * 16];         // per-chunk sum of e*V (64 ch)
__device__ float  g_aggE[NBLK];              // per-chunk sum of e
__device__ float4 g_sub [NBLK * NSUB * 16];  // EXCLUSIVE cross-sub EV prefix

// ---------------- K1: e-scores + chunk aggregates + sub prefixes (R8 base) --
__global__ __launch_bounds__(256, 8) void k_aggregate(
    const float* __restrict__ keys,
    const float* __restrict__ values,
    const float* __restrict__ w_score)
{
    __shared__ float sV[CH_ * E_];     // 16 KB V tile
    __shared__ float se[CH_];
    __shared__ float spEV[NSUB * E_];
    __shared__ float spE[NSUB];

    const int tid = threadIdx.x;
    const int blk = blockIdx.x;
    const int bh  = blk >> 5;          // / NC_
    const int c   = blk & 31;          // % NC_
    const int b   = bh >> 4;
    const int h   = bh & 15;
    const int base = ((b * L_ + c * CH_) * H_ + h) * E_;

    const int d   = tid & 63;
    const int sub = tid >> 6;
    const int r0  = sub * RPS;

    // e[row] = exp(0.125 * dot(K[row], w_k)); 4 threads per row
    {
        const int row = tid >> 2, q = tid & 3;
        const float4* kq = reinterpret_cast<const float4*>(
            keys + base + row * HE_ + q * 16);
        const float4* wq = reinterpret_cast<const float4*>(
            w_score + E_ + q * 16);
        float dot = 0.f;
        #pragma unroll
        for (int j = 0; j < 4; j++) {
            const float4 k4 = kq[j];
            const float4 w4 = wq[j];
            dot += k4.x * w4.x + k4.y * w4.y + k4.z * w4.z + k4.w * w4.w;
        }
        dot += __shfl_xor_sync(0xffffffffu, dot, 1);
        dot += __shfl_xor_sync(0xffffffffu, dot, 2);
        if (q == 0) {
            const float e = __expf(dot * 0.125f);
            se[row] = e;
            g_E[bh * L_ + c * CH_ + row] = e;
        }
    }

    // stage V tile (float4, coalesced)
    {
        const float4* vg = reinterpret_cast<const float4*>(values + base);
        float4* sv4 = reinterpret_cast<float4*>(sV);
        #pragma unroll
        for (int i = 0; i < 4; i++) {
            const int idx = tid + i * 256;
            sv4[idx] = vg[(idx >> 4) * (HE_ / 4) + (idx & 15)];
        }
    }
    __syncthreads();

    // per-sub partial aggregates over 16 rows
    {
        float sumE = 0.f, sumEV = 0.f;
        #pragma unroll
        for (int r = 0; r < RPS; r++) {
            const float e = se[r0 + r];
            sumE += e;
            sumEV = fmaf(e, sV[(r0 + r) * E_ + d], sumEV);
        }
        spEV[sub * E_ + d] = sumEV;
        if (d == 0) spE[sub] = sumE;
    }
    __syncthreads();

    // exclusive cross-sub prefix -> g_sub
    {
        float exc = 0.f;
        #pragma unroll
        for (int s = 0; s < NSUB - 1; s++)
            if (s < sub) exc += spEV[s * E_ + d];
        reinterpret_cast<float*>(g_sub)[(blk * NSUB + sub) * E_ + d] = exc;
    }

    // block aggregate
    if (tid < E_) {
        reinterpret_cast<float*>(g_agg)[blk * E_ + tid] =
            spEV[tid] + spEV[E_ + tid] + spEV[2 * E_ + tid] + spEV[3 * E_ + tid];
        if (tid == 0)
            g_aggE[blk] = spE[0] + spE[1] + spE[2] + spE[3];
    }
}

// ---------------- K2: float4 output scan (2 units of 64 threads) ------------
__global__ __launch_bounds__(128, 12) void k_output(
    const float* __restrict__ values,
    float* __restrict__ out)
{
    __shared__ float  se  [2][CH_];
    __shared__ float  srcp[2][CH_];
    __shared__ float4 sqEV[2][NSUB * 16];

    const int tid  = threadIdx.x;
    const int u    = tid >> 6;           // unit 0/1
    const int utid = tid & 63;
    const int blk  = blockIdx.x;         // 512 blocks
    const int bh   = blk >> 4;
    const int c    = ((blk & 15) << 1) + u;   // chunk 0..31
    const int b    = bh >> 4;
    const int h    = bh & 15;
    const int base = ((b * L_ + c * CH_) * H_ + h) * E_;

    const int sub = utid >> 4;           // 0..3 (16 rows each)
    const int d4  = utid & 15;           // float4 channel group

    // ---- E-side: first warp of each unit (thread-block 64-aligned => warp)
    if ((utid >> 5) == 0) {
        const int lane = utid & 31;
        float pe = (lane < c) ? g_aggE[bh * NC_ + lane] : 0.f;
        #pragma unroll
        for (int o = 16; o; o >>= 1) pe += __shfl_xor_sync(0xffffffffu, pe, o);
        const float2 e2 = reinterpret_cast<const float2*>(
            g_E + bh * L_ + c * CH_)[lane];
        const float p = e2.x + e2.y;
        float incl = p;
        #pragma unroll
        for (int o = 1; o < 32; o <<= 1) {
            const float t = __shfl_up_sync(0xffffffffu, incl, o);
            if (lane >= o) incl += t;
        }
        const float excl = incl - p;
        se[u][2 * lane]     = e2.x;
        se[u][2 * lane + 1] = e2.y;
        srcp[u][2 * lane]     = __fdividef(1.f, pe + excl + e2.x);
        srcp[u][2 * lane + 1] = __fdividef(1.f, pe + incl);
    }

    // ---- chunk-prefix EV (float4), split across 4 subs
    {
        float4 p = make_float4(0.f, 0.f, 0.f, 0.f);
        for (int t = sub; t < c; t += NSUB) {
            const float4 a = g_agg[(bh * NC_ + t) * 16 + d4];
            p.x += a.x; p.y += a.y; p.z += a.z; p.w += a.w;
        }
        sqEV[u][sub * 16 + d4] = p;
    }
    __syncthreads();

    // ---- exclusive start: one g_sub load + 4 smem combines
    float4 acc = g_sub[((bh * NC_ + c) * NSUB + sub) * 16 + d4];
    #pragma unroll
    for (int s = 0; s < NSUB; s++) {
        const float4 q = sqEV[u][s * 16 + d4];
        acc.x += q.x; acc.y += q.y; acc.z += q.z; acc.w += q.w;
    }

    // ---- inclusive scan over 16 rows; float4 loads/stores
    const int r0 = sub * RPS;
    const float4* v4 = reinterpret_cast<const float4*>(values + base);
    float4*       o4 = reinterpret_cast<float4*>(out + base);
    #pragma unroll 8
    for (int r = 0; r < RPS; r++) {
        const float e = se[u][r0 + r];
        const float4 vv = v4[(r0 + r) * (HE_ / 4) + d4];
        acc.x = fmaf(e, vv.x, acc.x);
        acc.y = fmaf(e, vv.y, acc.y);
        acc.z = fmaf(e, vv.z, acc.z);
        acc.w = fmaf(e, vv.w, acc.w);
        const float rc = srcp[u][r0 + r];
        float4 res;
        res.x = acc.x * rc; res.y = acc.y * rc;
        res.z = acc.z * rc; res.w = acc.w * rc;
        o4[(r0 + r) * (HE_ / 4) + d4] = res;
    }
}

extern "C" void kernel_launch(void* const* d_in, const int* in_sizes, int n_in,
                              void* d_out, int out_size) {
    // inputs: 0=queries (unused: a_q cancels in softmax), 1=keys, 2=values,
    //         3=w_score, 4=b_score (unused: cancels)
    const float* keys   = (const float*)d_in[1];
    const float* values = (const float*)d_in[2];
    const float* w      = (const float*)d_in[3];
    float* out = (float*)d_out;

    k_aggregate<<<NBLK, 256>>>(keys, values, w);
    k_output<<<512, 128>>>(values, out);
}

// round 11
// speedup vs baseline: 1.3303x; 1.3303x over previous
#include <cuda_runtime.h>
#include <math.h>

// Shape fixed by reference: B=2, L=2048, H=16, E=64
#define B_  2
#define L_  2048
#define H_  16
#define E_  64
#define BH_ 32            // B*H chains
#define CH_ 64            // chunk length along s
#define NC_ 32            // chunks per chain
#define HE_ 1024          // H*E row stride in floats
#define NBLK (BH_ * NC_)  // 1024 blocks
#define NSUB 4            // sub-groups (16 rows each)
#define RPS  16           // rows per sub (K1)

// Scratch (__device__ globals; no allocations allowed)
__device__ float  g_E   [BH_ * L_];          // e-scores
__device__ float4 g_agg [NBLK * 16];         // per-chunk sum of e*V (64 ch)
__device__ float  g_aggE[NBLK];              // per-chunk sum of e
__device__ float4 g_sub [NBLK * NSUB * 16];  // EXCLUSIVE cross-sub EV prefix

// ---------------- K1: e-scores + chunk aggregates + sub prefixes (R8 base) --
__global__ __launch_bounds__(256, 8) void k_aggregate(
    const float* __restrict__ keys,
    const float* __restrict__ values,
    const float* __restrict__ w_score)
{
    __shared__ float sV[CH_ * E_];     // 16 KB V tile
    __shared__ float se[CH_];
    __shared__ float spEV[NSUB * E_];
    __shared__ float spE[NSUB];

    const int tid = threadIdx.x;
    const int blk = blockIdx.x;
    const int bh  = blk >> 5;          // / NC_
    const int c   = blk & 31;          // % NC_
    const int b   = bh >> 4;
    const int h   = bh & 15;
    const int base = ((b * L_ + c * CH_) * H_ + h) * E_;

    const int d   = tid & 63;
    const int sub = tid >> 6;
    const int r0  = sub * RPS;

    // e[row] = exp(0.125 * dot(K[row], w_k)); 4 threads per row
    {
        const int row = tid >> 2, q = tid & 3;
        const float4* kq = reinterpret_cast<const float4*>(
            keys + base + row * HE_ + q * 16);
        const float4* wq = reinterpret_cast<const float4*>(
            w_score + E_ + q * 16);
        float dot = 0.f;
        #pragma unroll
        for (int j = 0; j < 4; j++) {
            const float4 k4 = kq[j];
            const float4 w4 = wq[j];
            dot += k4.x * w4.x + k4.y * w4.y + k4.z * w4.z + k4.w * w4.w;
        }
        dot += __shfl_xor_sync(0xffffffffu, dot, 1);
        dot += __shfl_xor_sync(0xffffffffu, dot, 2);
        if (q == 0) {
            const float e = __expf(dot * 0.125f);
            se[row] = e;
            g_E[bh * L_ + c * CH_ + row] = e;
        }
    }

    // stage V tile (float4, coalesced)
    {
        const float4* vg = reinterpret_cast<const float4*>(values + base);
        float4* sv4 = reinterpret_cast<float4*>(sV);
        #pragma unroll
        for (int i = 0; i < 4; i++) {
            const int idx = tid + i * 256;
            sv4[idx] = vg[(idx >> 4) * (HE_ / 4) + (idx & 15)];
        }
    }
    __syncthreads();

    // per-sub partial aggregates over 16 rows
    {
        float sumE = 0.f, sumEV = 0.f;
        #pragma unroll
        for (int r = 0; r < RPS; r++) {
            const float e = se[r0 + r];
            sumE += e;
            sumEV = fmaf(e, sV[(r0 + r) * E_ + d], sumEV);
        }
        spEV[sub * E_ + d] = sumEV;
        if (d == 0) spE[sub] = sumE;
    }
    __syncthreads();

    // exclusive cross-sub prefix -> g_sub
    {
        float exc = 0.f;
        #pragma unroll
        for (int s = 0; s < NSUB - 1; s++)
            if (s < sub) exc += spEV[s * E_ + d];
        reinterpret_cast<float*>(g_sub)[(blk * NSUB + sub) * E_ + d] = exc;
    }

    // block aggregate
    if (tid < E_) {
        reinterpret_cast<float*>(g_agg)[blk * E_ + tid] =
            spEV[tid] + spEV[E_ + tid] + spEV[2 * E_ + tid] + spEV[3 * E_ + tid];
        if (tid == 0)
            g_aggE[blk] = spE[0] + spE[1] + spE[2] + spE[3];
    }
}

// ---------------- K2: float4 output scan, 4 rows/thread, 256 thr/block -----
__global__ __launch_bounds__(256, 6) void k_output(
    const float* __restrict__ values,
    float* __restrict__ out)
{
    __shared__ float4 sPart[16 * 16];   // quad EV partials [q][d4]
    __shared__ float4 sPre [16 * 16];   // chunk-prefix partials [q][d4]
    __shared__ float  srcp[CH_];        // 1 / cumulative-E per row

    const int tid = threadIdx.x;
    const int blk = blockIdx.x;
    const int bh  = blk >> 5;
    const int c   = blk & 31;
    const int b   = bh >> 4;
    const int h   = bh & 15;
    const int base = ((b * L_ + c * CH_) * H_ + h) * E_;

    const int d4 = tid & 15;            // float4 channel group
    const int q  = tid >> 4;            // quad 0..15 (4 rows each)
    const int sub = q >> 2;             // 16-row sub
    const int qq  = q & 3;              // quad within sub
    const int r0  = q * 4;              // first row of quad

    // ---- warp 0: E-side reciprocals (independent of other phases)
    if (tid < 32) {
        const int lane = tid;
        float pe = (lane < c) ? g_aggE[bh * NC_ + lane] : 0.f;
        #pragma unroll
        for (int o = 16; o; o >>= 1) pe += __shfl_xor_sync(0xffffffffu, pe, o);
        const float2 e2 = reinterpret_cast<const float2*>(
            g_E + bh * L_ + c * CH_)[lane];
        const float p = e2.x + e2.y;
        float incl = p;
        #pragma unroll
        for (int o = 1; o < 32; o <<= 1) {
            const float t = __shfl_up_sync(0xffffffffu, incl, o);
            if (lane >= o) incl += t;
        }
        const float excl = incl - p;
        srcp[2 * lane]     = __fdividef(1.f, pe + excl + e2.x);
        srcp[2 * lane + 1] = __fdividef(1.f, pe + incl);
    }

    // ---- all threads: load own 4 e-scores (warp-broadcast L2 loads)
    float ev[4];
    #pragma unroll
    for (int j = 0; j < 4; j++)
        ev[j] = g_E[bh * L_ + c * CH_ + r0 + j];

    // ---- load 4 V float4 rows into regs (independent LDG.128s)
    const float4* v4 = reinterpret_cast<const float4*>(values + base);
    float4 vv[4];
    #pragma unroll
    for (int j = 0; j < 4; j++)
        vv[j] = v4[(r0 + j) * (HE_ / 4) + d4];

    // ---- quad EV partial
    {
        float4 p = make_float4(0.f, 0.f, 0.f, 0.f);
        #pragma unroll
        for (int j = 0; j < 4; j++) {
            p.x = fmaf(ev[j], vv[j].x, p.x);
            p.y = fmaf(ev[j], vv[j].y, p.y);
            p.z = fmaf(ev[j], vv[j].z, p.z);
            p.w = fmaf(ev[j], vv[j].w, p.w);
        }
        sPart[q * 16 + d4] = p;
    }

    // ---- chunk-prefix partial: terms t ≡ q (mod 16), t < c  (≤2 loads)
    {
        float4 p = make_float4(0.f, 0.f, 0.f, 0.f);
        #pragma unroll
        for (int k = 0; k < 2; k++) {
            const int t = q + k * 16;
            if (t < c) {
                const float4 a = g_agg[(bh * NC_ + t) * 16 + d4];
                p.x += a.x; p.y += a.y; p.z += a.z; p.w += a.w;
            }
        }
        sPre[q * 16 + d4] = p;
    }
    __syncthreads();

    // ---- exclusive start: g_sub + lower quads in sub + full chunk prefix
    float4 acc = g_sub[(blk * NSUB + sub) * 16 + d4];
    #pragma unroll
    for (int j = 0; j < 3; j++) {
        if (j < qq) {
            const float4 t = sPart[(sub * 4 + j) * 16 + d4];
            acc.x += t.x; acc.y += t.y; acc.z += t.z; acc.w += t.w;
        }
    }
    #pragma unroll
    for (int j = 0; j < 16; j++) {
        const float4 t = sPre[j * 16 + d4];
        acc.x += t.x; acc.y += t.y; acc.z += t.z; acc.w += t.w;
    }

    // ---- 4-row inclusive scan from regs; float4 stores
    float4* o4 = reinterpret_cast<float4*>(out + base);
    #pragma unroll
    for (int j = 0; j < 4; j++) {
        acc.x = fmaf(ev[j], vv[j].x, acc.x);
        acc.y = fmaf(ev[j], vv[j].y, acc.y);
        acc.z = fmaf(ev[j], vv[j].z, acc.z);
        acc.w = fmaf(ev[j], vv[j].w, acc.w);
        const float rc = srcp[r0 + j];
        float4 res;
        res.x = acc.x * rc; res.y = acc.y * rc;
        res.z = acc.z * rc; res.w = acc.w * rc;
        o4[(r0 + j) * (HE_ / 4) + d4] = res;
    }
}

extern "C" void kernel_launch(void* const* d_in, const int* in_sizes, int n_in,
                              void* d_out, int out_size) {
    // inputs: 0=queries (unused: a_q cancels in softmax), 1=keys, 2=values,
    //         3=w_score, 4=b_score (unused: cancels)
    const float* keys   = (const float*)d_in[1];
    const float* values = (const float*)d_in[2];
    const float* w      = (const float*)d_in[3];
    float* out = (float*)d_out;

    k_aggregate<<<NBLK, 256>>>(keys, values, w);
    k_output<<<NBLK, 256>>>(values, out);
}